// round 8
// baseline (speedup 1.0000x reference)
#include <cuda_runtime.h>
#include <cuda_bf16.h>
#include <cstdint>

#define N_NODES 50000
#define N_EDGES 400000
#define E_TOT   (N_EDGES + N_NODES)
#define G_GRAPHS 256
#define HC 200
#define C_CH 100
#define SLOPE 0.2f

#define TM_TILES 3125          // 50000 / 16 (exact)
#define TN_TILES 25            // 200 / 8 (exact)
#define KS16_MAX 21            // 336 / 16
#define NB_SCAN 196            // ceil(50000/256)

// dynamic smem for GEMM A-panel: hi+lo, 4 m-tiles x KS x 32 lanes x 16B
#define SMEM_GEMM_MAX (2 * 4 * KS16_MAX * 32 * 16)   // 86016 B

// ---------------- scratch (device globals; no allocation allowed) ------------
__device__ float g_h[(size_t)N_NODES * HC];
__device__ float g_x[(size_t)N_NODES * HC];
__device__ float g_es[N_NODES * 2];
__device__ float g_ed[N_NODES * 2];
__device__ float g_alpha[(size_t)E_TOT * 2];
__device__ int   g_rowptr[N_NODES + 1];
__device__ int   g_cnt[N_NODES];
__device__ int   g_fill[N_NODES];
__device__ int   g_colsrc[E_TOT];
__device__ float g_pool[G_GRAPHS * HC];
__device__ int   g_bsum[256];
__device__ int   g_boff[256];
// permuted bf16 hi/lo B operand in exact mma.m16n8k16 fragment order
__device__ uint2 g_pbh[(size_t)TN_TILES * KS16_MAX * 32];
__device__ uint2 g_pbl[(size_t)TN_TILES * KS16_MAX * 32];

// ---------------- CSR build --------------------------------------------------
__global__ void k_init_counts() {
    int i = blockIdx.x * blockDim.x + threadIdx.x;
    if (i < N_NODES) { g_cnt[i] = 1; g_fill[i] = 1; }
}

__global__ void k_count(const int* __restrict__ ei) {
    int e = blockIdx.x * blockDim.x + threadIdx.x;
    if (e < N_EDGES) atomicAdd(&g_cnt[ei[N_EDGES + e]], 1);
}

__global__ void k_scan1() {
    __shared__ int ws[8];
    int b = blockIdx.x, t = threadIdx.x;
    int i = b * 256 + t;
    int lane = t & 31, w = t >> 5;
    int v = (i < N_NODES) ? g_cnt[i] : 0;
    int s = v;
#pragma unroll
    for (int off = 1; off < 32; off <<= 1) {
        int u = __shfl_up_sync(0xffffffffu, s, off);
        if (lane >= off) s += u;
    }
    if (lane == 31) ws[w] = s;
    __syncthreads();
    if (t == 0) {
        int run = 0;
#pragma unroll
        for (int j = 0; j < 8; j++) { int tmp = ws[j]; ws[j] = run; run += tmp; }
        g_bsum[b] = run;
    }
    __syncthreads();
    if (i < N_NODES) g_rowptr[i + 1] = s + ws[w];
}

__global__ void k_scan2() {
    __shared__ int ws[8];
    int t = threadIdx.x;
    int lane = t & 31, w = t >> 5;
    int v = (t < NB_SCAN) ? g_bsum[t] : 0;
    int s = v;
#pragma unroll
    for (int off = 1; off < 32; off <<= 1) {
        int u = __shfl_up_sync(0xffffffffu, s, off);
        if (lane >= off) s += u;
    }
    if (lane == 31) ws[w] = s;
    __syncthreads();
    if (t == 0) {
        int run = 0;
#pragma unroll
        for (int j = 0; j < 8; j++) { int tmp = ws[j]; ws[j] = run; run += tmp; }
    }
    __syncthreads();
    if (t < NB_SCAN) g_boff[t] = s + ws[w] - v;
}

__global__ void k_scan3() {
    int i = blockIdx.x * blockDim.x + threadIdx.x;
    if (i == 0) g_rowptr[0] = 0;
    if (i < N_NODES) g_rowptr[i + 1] += g_boff[i >> 8];
}

__global__ void k_selfloop() {
    int i = blockIdx.x * blockDim.x + threadIdx.x;
    if (i < N_NODES) g_colsrc[g_rowptr[i]] = i;
}

__global__ void k_fill(const int* __restrict__ ei) {
    int e = blockIdx.x * blockDim.x + threadIdx.x;
    if (e < N_EDGES) {
        int d = ei[N_EDGES + e];
        int pos = g_rowptr[d] + atomicAdd(&g_fill[d], 1);
        g_colsrc[pos] = ei[e];
    }
}

// ---------------- bf16 helpers -----------------------------------------------
__device__ __forceinline__ uint32_t packbf(float a, float b) {
    __nv_bfloat162 p = __floats2bfloat162_rn(a, b);
    return *(uint32_t*)&p;
}
__device__ __forceinline__ float bfhi(float v) {
    return __bfloat162float(__float2bfloat16_rn(v));
}

__device__ __forceinline__ void mma_bf16(float& c0, float& c1, float& c2, float& c3,
                                         uint32_t a0, uint32_t a1, uint32_t a2, uint32_t a3,
                                         uint32_t b0, uint32_t b1) {
    asm volatile(
        "mma.sync.aligned.m16n8k16.row.col.f32.bf16.bf16.f32 "
        "{%0,%1,%2,%3},{%4,%5,%6,%7},{%8,%9},{%0,%1,%2,%3};"
        : "+f"(c0), "+f"(c1), "+f"(c2), "+f"(c3)
        : "r"(a0), "r"(a1), "r"(a2), "r"(a3), "r"(b0), "r"(b1));
}

// B fragment prep: b0={B[k0][n],B[k0+1][n]}, b1={B[k0+8][n],B[k0+9][n]}
__global__ void k_convB(const float* __restrict__ B, int K, int KS, int total) {
    int t = blockIdx.x * blockDim.x + threadIdx.x;
    if (t >= total) return;
    int lane = t & 31;
    int rest = t >> 5;
    int ks = rest % KS;
    int tn = rest / KS;
    int groupr = lane >> 2, kc = lane & 3;
    int n = tn * 8 + groupr;
    int k0 = ks * 16 + kc * 2;
    float v[4];
#pragma unroll
    for (int j = 0; j < 4; j++) {
        int k = k0 + (j >> 1) * 8 + (j & 1);
        v[j] = (k < K) ? B[(size_t)k * HC + n] : 0.f;
    }
    float h[4], l[4];
#pragma unroll
    for (int j = 0; j < 4; j++) { h[j] = bfhi(v[j]); l[j] = v[j] - h[j]; }
    g_pbh[t] = make_uint2(packbf(h[0], h[1]), packbf(h[2], h[3]));
    g_pbl[t] = make_uint2(packbf(l[0], l[1]), packbf(l[2], l[3]));
}

// ---------------- fused-conversion smem GEMM ---------------------------------
// block tile: 64 rows (4 m-tiles) x 128 cols (16 n-tiles); grid (2, 782).
// A panel staged ONCE into smem as bf16 hi/lo in exact fragment order,
// then warps (2m x 4n) run the MMA loop with LDS.128 fragment reads.
__global__ void __launch_bounds__(256)
k_gemm_smem(const float* __restrict__ Aext, int useExt, int K, int KS) {
    extern __shared__ uint4 sA[];                // [hi: 4*KS*32][lo: 4*KS*32]
    const float* A = useExt ? Aext : g_x;
    int tid = threadIdx.x;
    int rowBase = blockIdx.y * 64;
    uint4* sAh = sA;
    uint4* sAl = sA + 4 * KS * 32;

    // ---- stage + convert A panel (fragment order) ----
    int total = 4 * KS * 32;
    for (int i = tid; i < total; i += 256) {
        int lane = i & 31;
        int tmp = i >> 5;
        int ks = tmp % KS;
        int mtl = tmp / KS;
        int groupr = lane >> 2, kc = lane & 3;
        int r0 = rowBase + mtl * 16 + groupr;
        int r1 = r0 + 8;
        int k0 = ks * 16 + kc * 2;
        float2 p00 = make_float2(0.f, 0.f), p01 = p00, p10 = p00, p11 = p00;
        if (r0 < N_NODES) {
            const float* p = A + (size_t)r0 * K;
            if (k0 + 1 < K) p00 = *(const float2*)(p + k0);
            if (k0 + 9 < K) p01 = *(const float2*)(p + k0 + 8);
        }
        if (r1 < N_NODES) {
            const float* p = A + (size_t)r1 * K;
            if (k0 + 1 < K) p10 = *(const float2*)(p + k0);
            if (k0 + 9 < K) p11 = *(const float2*)(p + k0 + 8);
        }
        float h00x = bfhi(p00.x), h00y = bfhi(p00.y);
        float h10x = bfhi(p10.x), h10y = bfhi(p10.y);
        float h01x = bfhi(p01.x), h01y = bfhi(p01.y);
        float h11x = bfhi(p11.x), h11y = bfhi(p11.y);
        sAh[i] = make_uint4(packbf(h00x, h00y), packbf(h10x, h10y),
                            packbf(h01x, h01y), packbf(h11x, h11y));
        sAl[i] = make_uint4(packbf(p00.x - h00x, p00.y - h00y),
                            packbf(p10.x - h10x, p10.y - h10y),
                            packbf(p01.x - h01x, p01.y - h01y),
                            packbf(p11.x - h11x, p11.y - h11y));
    }
    __syncthreads();

    // ---- MMA mainloop ----
    int lane = tid & 31, warp = tid >> 5;
    int wm = warp & 1, wn = warp >> 1;            // 2m x 4n warps
    int tnB = blockIdx.x * 16 + wn * 4;
    if (tnB >= TN_TILES) return;                  // after the barrier: safe

    int mtl0 = wm * 2;
    bool nv[4];
#pragma unroll
    for (int ni = 0; ni < 4; ni++) nv[ni] = (tnB + ni) < TN_TILES;
    size_t bBase[4];
#pragma unroll
    for (int ni = 0; ni < 4; ni++) bBase[ni] = ((size_t)(tnB + ni) * KS) * 32 + lane;

    int aIdx0 = (mtl0 * KS) * 32 + lane;
    int aIdx1 = ((mtl0 + 1) * KS) * 32 + lane;

    float acc[2][4][4];
#pragma unroll
    for (int mi = 0; mi < 2; mi++)
#pragma unroll
        for (int ni = 0; ni < 4; ni++)
#pragma unroll
            for (int r = 0; r < 4; r++) acc[mi][ni][r] = 0.f;

    const uint2 z2 = make_uint2(0, 0);

#pragma unroll 2
    for (int ks = 0; ks < KS; ks++) {
        int soff = ks * 32;
        uint4 ah0 = sAh[aIdx0 + soff];
        uint4 al0 = sAl[aIdx0 + soff];
        uint4 ah1 = sAh[aIdx1 + soff];
        uint4 al1 = sAl[aIdx1 + soff];
        size_t goff = (size_t)ks * 32;
        uint2 bh[4], bl[4];
#pragma unroll
        for (int ni = 0; ni < 4; ni++) {
            bh[ni] = nv[ni] ? g_pbh[bBase[ni] + goff] : z2;
            bl[ni] = nv[ni] ? g_pbl[bBase[ni] + goff] : z2;
        }
#pragma unroll
        for (int ni = 0; ni < 4; ni++) {
            {
                float* c = acc[0][ni];
                mma_bf16(c[0], c[1], c[2], c[3], ah0.x, ah0.y, ah0.z, ah0.w, bh[ni].x, bh[ni].y);
                mma_bf16(c[0], c[1], c[2], c[3], al0.x, al0.y, al0.z, al0.w, bh[ni].x, bh[ni].y);
                mma_bf16(c[0], c[1], c[2], c[3], ah0.x, ah0.y, ah0.z, ah0.w, bl[ni].x, bl[ni].y);
            }
            {
                float* c = acc[1][ni];
                mma_bf16(c[0], c[1], c[2], c[3], ah1.x, ah1.y, ah1.z, ah1.w, bh[ni].x, bh[ni].y);
                mma_bf16(c[0], c[1], c[2], c[3], al1.x, al1.y, al1.z, al1.w, bh[ni].x, bh[ni].y);
                mma_bf16(c[0], c[1], c[2], c[3], ah1.x, ah1.y, ah1.z, ah1.w, bl[ni].x, bl[ni].y);
            }
        }
    }

    // ---- epilogue ----
    int groupr = lane >> 2, kc = lane & 3;
#pragma unroll
    for (int mi = 0; mi < 2; mi++) {
        int r = rowBase + (mtl0 + mi) * 16 + groupr;
        if (r >= N_NODES) continue;
        bool r8ok = (r + 8) < N_NODES;
#pragma unroll
        for (int ni = 0; ni < 4; ni++) {
            if (!nv[ni]) continue;
            int c = (tnB + ni) * 8 + kc * 2;
            g_h[(size_t)r * HC + c]           = acc[mi][ni][0];
            g_h[(size_t)r * HC + c + 1]       = acc[mi][ni][1];
            if (r8ok) {
                g_h[(size_t)(r + 8) * HC + c]     = acc[mi][ni][2];
                g_h[(size_t)(r + 8) * HC + c + 1] = acc[mi][ni][3];
            }
        }
    }
}

// ---------------- per-node attention scores ----------------------------------
__global__ void k_scores(const float* __restrict__ a_s, const float* __restrict__ a_d) {
    int gwarp = (blockIdx.x * blockDim.x + threadIdx.x) >> 5;
    int lane = threadIdx.x & 31;
    if (gwarp >= N_NODES) return;
    const float* hr = g_h + (size_t)gwarp * HC;
    float s0s = 0.f, s1s = 0.f, s0d = 0.f, s1d = 0.f;
#pragma unroll
    for (int k = 0; k < 7; k++) {
        int c = lane + 32 * k;
        if (c < HC) {
            float v = hr[c];
            float vs = v * a_s[c], vd = v * a_d[c];
            if (c < C_CH) { s0s += vs; s0d += vd; }
            else          { s1s += vs; s1d += vd; }
        }
    }
#pragma unroll
    for (int off = 16; off; off >>= 1) {
        s0s += __shfl_xor_sync(0xffffffffu, s0s, off);
        s1s += __shfl_xor_sync(0xffffffffu, s1s, off);
        s0d += __shfl_xor_sync(0xffffffffu, s0d, off);
        s1d += __shfl_xor_sync(0xffffffffu, s1d, off);
    }
    if (lane == 0) {
        g_es[gwarp * 2 + 0] = s0s; g_es[gwarp * 2 + 1] = s1s;
        g_ed[gwarp * 2 + 0] = s0d; g_ed[gwarp * 2 + 1] = s1d;
    }
}

__device__ __forceinline__ float lrelu(float v) { return v >= 0.f ? v : SLOPE * v; }

// ---------------- warp-per-dst softmax + aggregate + bias + relu -------------
__global__ void k_aggregate(const float* __restrict__ bias) {
    int n = (blockIdx.x * blockDim.x + threadIdx.x) >> 5;
    int lane = threadIdx.x & 31;
    if (n >= N_NODES) return;
    int beg = g_rowptr[n], end = g_rowptr[n + 1];
    float ed0 = g_ed[n * 2 + 0], ed1 = g_ed[n * 2 + 1];

    float m0 = -1e30f, m1 = -1e30f;
    for (int i = beg + lane; i < end; i += 32) {
        int s = g_colsrc[i];
        m0 = fmaxf(m0, lrelu(g_es[s * 2 + 0] + ed0));
        m1 = fmaxf(m1, lrelu(g_es[s * 2 + 1] + ed1));
    }
#pragma unroll
    for (int off = 16; off; off >>= 1) {
        m0 = fmaxf(m0, __shfl_xor_sync(0xffffffffu, m0, off));
        m1 = fmaxf(m1, __shfl_xor_sync(0xffffffffu, m1, off));
    }

    float s0 = 0.f, s1 = 0.f;
    for (int i = beg + lane; i < end; i += 32) {
        int s = g_colsrc[i];
        float p0 = __expf(lrelu(g_es[s * 2 + 0] + ed0) - m0);
        float p1 = __expf(lrelu(g_es[s * 2 + 1] + ed1) - m1);
        ((float2*)g_alpha)[i] = make_float2(p0, p1);
        s0 += p0;
        s1 += p1;
    }
    __threadfence_block();
#pragma unroll
    for (int off = 16; off; off >>= 1) {
        s0 += __shfl_xor_sync(0xffffffffu, s0, off);
        s1 += __shfl_xor_sync(0xffffffffu, s1, off);
    }
    float inv0 = 1.f / (s0 + 1e-16f), inv1 = 1.f / (s1 + 1e-16f);

    float acc[7];
#pragma unroll
    for (int k = 0; k < 7; k++) acc[k] = 0.f;

    for (int i = beg; i < end; i++) {
        int s = g_colsrc[i];
        float2 p = ((const float2*)g_alpha)[i];
        float a0 = p.x * inv0;
        float a1 = p.y * inv1;
        const float* hr = g_h + (size_t)s * HC;
#pragma unroll
        for (int k = 0; k < 7; k++) {
            int c = lane + 32 * k;
            if (c < HC) acc[k] += (c < C_CH ? a0 : a1) * hr[c];
        }
    }
#pragma unroll
    for (int k = 0; k < 7; k++) {
        int c = lane + 32 * k;
        if (c < HC) {
            float v = acc[k] + bias[c];
            g_x[(size_t)n * HC + c] = v > 0.f ? v : 0.f;
        }
    }
}

// ---------------- global mean pool (batch sorted -> segment reduce) ----------
__global__ void k_pool_seg(const int* __restrict__ batch) {
    int g = blockIdx.x;
    int t = threadIdx.x;
    int lo = 0, hi = N_NODES;
    while (lo < hi) { int m = (lo + hi) >> 1; if (batch[m] < g) lo = m + 1; else hi = m; }
    int beg = lo;
    hi = N_NODES;
    while (lo < hi) { int m = (lo + hi) >> 1; if (batch[m] < g + 1) lo = m + 1; else hi = m; }
    int end = lo;
    float inv = 1.f / fmaxf((float)(end - beg), 1.f);
    for (int c = t; c < HC; c += blockDim.x) {
        float s = 0.f;
        for (int n = beg; n < end; n++) s += g_x[(size_t)n * HC + c];
        g_pool[g * HC + c] = s * inv;
    }
}

// ---------------- fused MLP head ---------------------------------------------
__global__ void k_mlp(const float* __restrict__ lw1, const float* __restrict__ lb1,
                      const float* __restrict__ lw2, const float* __restrict__ lb2,
                      const float* __restrict__ lw3, const float* __restrict__ lb3,
                      float* __restrict__ out) {
    int g = blockIdx.x;
    int t = threadIdx.x;
    __shared__ float buf[HC];
    __shared__ float t1[100];
    __shared__ float t2[100];
    for (int k = t; k < HC; k += blockDim.x) buf[k] = g_pool[g * HC + k];
    __syncthreads();
    if (t < 100) {
        float s = lb1[t];
        for (int k = 0; k < HC; k++) s += buf[k] * lw1[k * 100 + t];
        t1[t] = fmaxf(s, 0.f);
    }
    __syncthreads();
    if (t < 100) {
        float s = lb2[t];
        for (int k = 0; k < 100; k++) s += t1[k] * lw2[k * 100 + t];
        t2[t] = fmaxf(s, 0.f);
    }
    __syncthreads();
    if (t < 29) {
        float s = lb3[t];
        for (int k = 0; k < 100; k++) s += t2[k] * lw3[k * 29 + t];
        out[g * 29 + t] = s;
    }
}

// ---------------- launch ------------------------------------------------------
extern "C" void kernel_launch(void* const* d_in, const int* in_sizes, int n_in,
                              void* d_out, int out_size) {
    const float* x     = (const float*)d_in[0];
    const int*   ei    = (const int*)d_in[1];
    const int*   batch = (const int*)d_in[2];
    const float* W[5];
    const float* Asr[5];
    const float* Ads[5];
    const float* Bc[5];
    for (int i = 0; i < 5; i++) {
        W[i]   = (const float*)d_in[3 + 4 * i];
        Asr[i] = (const float*)d_in[4 + 4 * i];
        Ads[i] = (const float*)d_in[5 + 4 * i];
        Bc[i]  = (const float*)d_in[6 + 4 * i];
    }
    const float* lw1 = (const float*)d_in[23];
    const float* lb1 = (const float*)d_in[24];
    const float* lw2 = (const float*)d_in[25];
    const float* lb2 = (const float*)d_in[26];
    const float* lw3 = (const float*)d_in[27];
    const float* lb3 = (const float*)d_in[28];
    float* out = (float*)d_out;

    cudaFuncSetAttribute(k_gemm_smem, cudaFuncAttributeMaxDynamicSharedMemorySize,
                         SMEM_GEMM_MAX);

    k_init_counts<<<(N_NODES + 255) / 256, 256>>>();
    k_count<<<(N_EDGES + 255) / 256, 256>>>(ei);
    k_scan1<<<NB_SCAN, 256>>>();
    k_scan2<<<1, 256>>>();
    k_scan3<<<(N_NODES + 255) / 256, 256>>>();
    k_selfloop<<<(N_NODES + 255) / 256, 256>>>();
    k_fill<<<(N_EDGES + 255) / 256, 256>>>(ei);

    int Kdims[5] = {336, 200, 200, 200, 200};
    int wblocks = (N_NODES + 7) / 8;
    dim3 gemmGrid(2, (N_NODES + 63) / 64);

    for (int L = 0; L < 5; L++) {
        int K = Kdims[L];
        int KS = (K + 15) / 16;
        int totB = TN_TILES * KS * 32;
        size_t smemBytes = (size_t)2 * 4 * KS * 32 * 16;
        k_convB<<<(totB + 255) / 256, 256>>>(W[L], K, KS, totB);
        k_gemm_smem<<<gemmGrid, 256, smemBytes>>>(x, L == 0 ? 1 : 0, K, KS);
        k_scores<<<wblocks, 256>>>(Asr[L], Ads[L]);
        k_aggregate<<<wblocks, 256>>>(Bc[L]);
    }
    k_pool_seg<<<G_GRAPHS, 256>>>(batch);
    k_mlp<<<G_GRAPHS, 128>>>(lw1, lb1, lw2, lb2, lw3, lb3, out);
}